// round 3
// baseline (speedup 1.0000x reference)
#include <cuda_runtime.h>
#include <cuda_bf16.h>

// 2-layer GCN: x[50000,64], edge_index[2,800000], W1[64,64], b1[64],
// W2[64,16], b2[16] -> out[50000,16] f32.
//
// edge_index dtype is detected at runtime (int32 vs int64): JAX with x64
// disabled silently demotes jnp.int64 to int32, and reading int32 data as
// int64 produced garbage addresses -> trap 717 in rounds 1-2.
//
// Pipeline: detect dtype -> normalize edges to int32 -> CSR by dst (int
// atomics) -> GEMM1 (dinv-scaled epilogue) -> warp-per-node gather agg with
// fused relu/bias -> GEMM2 -> gather agg -> out. No float atomics anywhere.

#define NN 50000
#define FIN 64
#define HID 64
#define NCLS 16
#define EMAX 800000

__device__ int   g_is32;           // 1 if edge_index is int32
__device__ int   g_src[EMAX];      // normalized src indices
__device__ int   g_dst[EMAX];      // normalized dst indices
__device__ int   g_cnt[NN];        // in-degree histogram (by dst)
__device__ int   g_off[NN + 1];    // CSR offsets
__device__ int   g_pos[NN];        // running fill positions
__device__ int   g_esrc[EMAX];     // src node per CSR slot
__device__ float g_dinv[NN];       // rsqrt(deg+1)
__device__ float g_h1[NN * HID];   // (x@W1) * dinv[row]
__device__ float g_act1[NN * HID]; // relu layer-1 output
__device__ float g_h2[NN * NCLS];  // (act1@W2) * dinv[row]

// ---- detect dtype: int64 reads of int32 pairs are >= 2^32 w.p. ~1 ----
__global__ void k_detect(const long long* __restrict__ ei) {
    long long v = ei[threadIdx.x];  // 64 threads
    if (v < 0 || v >= NN) atomicOr(&g_is32, 1);
}

// ---- normalize edges to int32, clamped to valid range ----
__global__ void k_convert(const void* __restrict__ ei, int E) {
    int e = blockIdx.x * blockDim.x + threadIdx.x;
    if (e >= E) return;
    int s, d;
    if (g_is32) {
        const int* p = (const int*)ei;
        s = p[e]; d = p[E + e];
    } else {
        const long long* p = (const long long*)ei;
        s = (int)p[e]; d = (int)p[E + e];
    }
    if (s < 0) s = 0; if (s >= NN) s = NN - 1;
    if (d < 0) d = 0; if (d >= NN) d = NN - 1;
    g_src[e] = s;
    g_dst[e] = d;
}

// ---- zero histogram + dtype flag ----
__global__ void k_zero(int n) {
    int i = blockIdx.x * blockDim.x + threadIdx.x;
    if (i < n) g_cnt[i] = 0;
    if (i == 0) g_is32 = 0;
}

// ---- histogram of dst ----
__global__ void k_hist(int E) {
    int e = blockIdx.x * blockDim.x + threadIdx.x;
    if (e < E) atomicAdd(&g_cnt[g_dst[e]], 1);
}

// ---- single-block exclusive scan; also dinv = rsqrt(deg+1) ----
__global__ void k_scan(int n) {
    __shared__ int partial[1024];
    int t = threadIdx.x;
    int chunk = (n + 1023) / 1024;
    int lo = t * chunk;
    int hi = lo + chunk; if (hi > n) hi = n;
    if (lo > n) lo = n;
    int s = 0;
    for (int i = lo; i < hi; i++) s += g_cnt[i];
    partial[t] = s;
    __syncthreads();
    for (int d = 1; d < 1024; d <<= 1) {
        int v = (t >= d) ? partial[t - d] : 0;
        __syncthreads();
        partial[t] += v;
        __syncthreads();
    }
    int base = (t == 0) ? 0 : partial[t - 1];
    for (int i = lo; i < hi; i++) {
        int c = g_cnt[i];
        g_off[i] = base;
        g_pos[i] = base;
        g_dinv[i] = rsqrtf((float)c + 1.0f);
        base += c;
    }
    if (hi == n) g_off[n] = base;
}

// ---- fill CSR ----
__global__ void k_fill(int E) {
    int e = blockIdx.x * blockDim.x + threadIdx.x;
    if (e >= E) return;
    int p = atomicAdd(&g_pos[g_dst[e]], 1);
    if (p >= 0 && p < EMAX) g_esrc[p] = g_src[e];
}

// ---- GEMM1: h1[r,:] = (x[r,:] @ W1) * dinv[r] ----
__global__ void k_gemm1(const float* __restrict__ x, const float* __restrict__ W,
                        int n) {
    __shared__ float Ws[FIN * HID];
    __shared__ float xs[32][FIN];
    int t = threadIdx.x;
    for (int i = t; i < FIN * HID; i += 256) Ws[i] = W[i];
    int row0 = blockIdx.x * 32;
    for (int i = t; i < 32 * FIN; i += 256) {
        int r = i >> 6, k = i & 63;
        int gr = row0 + r;
        xs[r][k] = (gr < n) ? x[gr * FIN + k] : 0.0f;
    }
    __syncthreads();

    int c = t & 63;
    int rbase = t >> 6;
    float acc[8];
#pragma unroll
    for (int j = 0; j < 8; j++) acc[j] = 0.0f;
#pragma unroll
    for (int k = 0; k < FIN; k++) {
        float w = Ws[k * HID + c];
#pragma unroll
        for (int j = 0; j < 8; j++)
            acc[j] += xs[rbase + 4 * j][k] * w;
    }
#pragma unroll
    for (int j = 0; j < 8; j++) {
        int r = row0 + rbase + 4 * j;
        if (r < n) g_h1[r * HID + c] = acc[j] * g_dinv[r];
    }
}

// ---- aggregate layer 1: warp per node, fused relu((sum+self)*dinv + b1) ----
__global__ void k_agg1(const float* __restrict__ b1, int n) {
    int node = blockIdx.x * 8 + (threadIdx.x >> 5);
    if (node >= n) return;
    int lane = threadIdx.x & 31;
    int e = g_off[node];
    int end = g_off[node + 1];
    float a0 = 0.0f, a1 = 0.0f;
    for (; e < end; e++) {
        int s = g_esrc[e];
        const float* row = g_h1 + s * HID;
        a0 += row[lane];
        a1 += row[lane + 32];
    }
    float di = g_dinv[node];
    const float* self = g_h1 + node * HID;
    float v0 = (a0 + self[lane]) * di + b1[lane];
    float v1 = (a1 + self[lane + 32]) * di + b1[lane + 32];
    g_act1[node * HID + lane]      = v0 > 0.0f ? v0 : 0.0f;
    g_act1[node * HID + lane + 32] = v1 > 0.0f ? v1 : 0.0f;
}

// ---- GEMM2: h2[r,:] = (act1[r,:] @ W2) * dinv[r] ----
__global__ void k_gemm2(const float* __restrict__ W, int n) {
    __shared__ float Ws[HID * NCLS];
    __shared__ float xs[64][HID + 1];
    int t = threadIdx.x;
    for (int i = t; i < HID * NCLS; i += 256) Ws[i] = W[i];
    int row0 = blockIdx.x * 64;
    for (int i = t; i < 64 * HID; i += 256) {
        int r = i >> 6, k = i & 63;
        int gr = row0 + r;
        xs[r][k] = (gr < n) ? g_act1[gr * HID + k] : 0.0f;
    }
    __syncthreads();

    int c = t & 15;
    int rt = t >> 4;
    float acc[4];
#pragma unroll
    for (int j = 0; j < 4; j++) acc[j] = 0.0f;
#pragma unroll
    for (int k = 0; k < HID; k++) {
        float w = Ws[k * NCLS + c];
#pragma unroll
        for (int j = 0; j < 4; j++)
            acc[j] += xs[rt + 16 * j][k] * w;
    }
#pragma unroll
    for (int j = 0; j < 4; j++) {
        int r = row0 + rt + 16 * j;
        if (r < n) g_h2[r * NCLS + c] = acc[j] * g_dinv[r];
    }
}

// ---- aggregate layer 2: half-warp per node ----
__global__ void k_agg2(const float* __restrict__ b2, float* __restrict__ out, int n) {
    int node = blockIdx.x * 16 + (threadIdx.x >> 4);
    if (node >= n) return;
    int lane = threadIdx.x & 15;
    int e = g_off[node];
    int end = g_off[node + 1];
    float a = 0.0f;
    for (; e < end; e++) {
        a += g_h2[g_esrc[e] * NCLS + lane];
    }
    float di = g_dinv[node];
    out[node * NCLS + lane] = (a + g_h2[node * NCLS + lane]) * di + b2[lane];
}

extern "C" void kernel_launch(void* const* d_in, const int* in_sizes, int n_in,
                              void* d_out, int out_size) {
    const float* x = (const float*)d_in[0];
    const void* ei = d_in[1];
    const float* W1 = (const float*)d_in[2];
    const float* b1 = (const float*)d_in[3];
    const float* W2 = (const float*)d_in[4];
    const float* b2 = (const float*)d_in[5];
    float* out = (float*)d_out;

    int n = in_sizes[0] / FIN;   // 50000
    int E = in_sizes[1] / 2;     // 800000

    k_zero<<<(n + 255) / 256, 256>>>(n);
    k_detect<<<1, 64>>>((const long long*)ei);
    k_convert<<<(E + 255) / 256, 256>>>(ei, E);
    k_hist<<<(E + 255) / 256, 256>>>(E);
    k_scan<<<1, 1024>>>(n);
    k_fill<<<(E + 255) / 256, 256>>>(E);

    k_gemm1<<<(n + 31) / 32, 256>>>(x, W1, n);
    k_agg1<<<(n + 7) / 8, 256>>>(b1, n);

    k_gemm2<<<(n + 63) / 64, 256>>>(W2, n);
    k_agg2<<<(n + 15) / 16, 256>>>(b2, out, n);
}

// round 4
// speedup vs baseline: 1.1906x; 1.1906x over previous
#include <cuda_runtime.h>
#include <cuda_bf16.h>

// 2-layer GCN: x[50000,64], edge_index[2,800000], W1[64,64], b1[64],
// W2[64,16], b2[16] -> out[50000,16] f32.
//
// R3 passed @203us. R4: remove edge-normalization pass (read edge_index
// directly with runtime dtype branch), unroll gather loops for MLP, slim the
// serial scan. CSR-by-dst + gather aggregation, no float atomics.

#define NN 50000
#define FIN 64
#define HID 64
#define NCLS 16
#define EMAX 800000

__device__ int   g_is32;           // 1 if edge_index is int32
__device__ int   g_cnt[NN];        // in-degree histogram (by dst)
__device__ int   g_off[NN + 1];    // CSR offsets
__device__ int   g_pos[NN];        // running fill positions
__device__ int   g_esrc[EMAX];     // src node per CSR slot
__device__ float g_dinv[NN];       // rsqrt(deg+1)
__device__ float g_h1[NN * HID];   // (x@W1) * dinv[row]
__device__ float g_act1[NN * HID]; // relu layer-1 output
__device__ float g_h2[NN * NCLS];  // (act1@W2) * dinv[row]

// ---- index fetch helpers (dtype-branched, clamped) ----
__device__ __forceinline__ int load_idx(const void* ei, int i, int is32) {
    int v;
    if (is32) v = ((const int*)ei)[i];
    else      v = (int)((const long long*)ei)[i];
    if (v < 0) v = 0;
    if (v >= NN) v = NN - 1;
    return v;
}

// ---- zero histogram + detect dtype in one launch ----
// int64 reads of int32 pairs land outside [0,NN) w.p. ~1.
__global__ void k_zero_detect(const long long* __restrict__ ei, int n) {
    int i = blockIdx.x * blockDim.x + threadIdx.x;
    if (i < n) g_cnt[i] = 0;
    if (blockIdx.x == 0 && threadIdx.x == 0) g_is32 = 0;
}
__global__ void k_detect(const long long* __restrict__ ei) {
    long long v = ei[threadIdx.x];  // 64 threads
    if (v < 0 || v >= NN) atomicOr(&g_is32, 1);
}

// ---- histogram of dst directly from edge_index ----
__global__ void k_hist(const void* __restrict__ ei, int E) {
    int e = blockIdx.x * blockDim.x + threadIdx.x;
    if (e >= E) return;
    int d = load_idx(ei, E + e, g_is32);
    atomicAdd(&g_cnt[d], 1);
}

// ---- dinv = rsqrt(deg+1), parallel ----
__global__ void k_dinv(int n) {
    int i = blockIdx.x * blockDim.x + threadIdx.x;
    if (i < n) g_dinv[i] = rsqrtf((float)g_cnt[i] + 1.0f);
}

// ---- single-block exclusive scan of g_cnt -> g_off, g_pos ----
__global__ void k_scan(int n) {
    __shared__ int partial[1024];
    int t = threadIdx.x;
    int chunk = (n + 1023) / 1024;
    int lo = t * chunk;
    int hi = lo + chunk; if (hi > n) hi = n;
    if (lo > n) lo = n;
    int s = 0;
    for (int i = lo; i < hi; i++) s += g_cnt[i];
    partial[t] = s;
    __syncthreads();
    for (int d = 1; d < 1024; d <<= 1) {
        int v = (t >= d) ? partial[t - d] : 0;
        __syncthreads();
        partial[t] += v;
        __syncthreads();
    }
    int base = (t == 0) ? 0 : partial[t - 1];
    for (int i = lo; i < hi; i++) {
        int c = g_cnt[i];
        g_off[i] = base;
        g_pos[i] = base;
        base += c;
    }
    if (hi == n) g_off[n] = base;
}

// ---- fill CSR directly from edge_index ----
__global__ void k_fill(const void* __restrict__ ei, int E) {
    int e = blockIdx.x * blockDim.x + threadIdx.x;
    if (e >= E) return;
    int is32 = g_is32;
    int s = load_idx(ei, e, is32);
    int d = load_idx(ei, E + e, is32);
    int p = atomicAdd(&g_pos[d], 1);
    if (p >= 0 && p < EMAX) g_esrc[p] = s;
}

// ---- GEMM1: h1[r,:] = (x[r,:] @ W1) * dinv[r] ----
__global__ void k_gemm1(const float* __restrict__ x, const float* __restrict__ W,
                        int n) {
    __shared__ float Ws[FIN * HID];
    __shared__ float xs[32][FIN];
    int t = threadIdx.x;
    for (int i = t; i < FIN * HID; i += 256) Ws[i] = W[i];
    int row0 = blockIdx.x * 32;
    for (int i = t; i < 32 * FIN; i += 256) {
        int r = i >> 6, k = i & 63;
        int gr = row0 + r;
        xs[r][k] = (gr < n) ? x[gr * FIN + k] : 0.0f;
    }
    __syncthreads();

    int c = t & 63;
    int rbase = t >> 6;
    float acc[8];
#pragma unroll
    for (int j = 0; j < 8; j++) acc[j] = 0.0f;
#pragma unroll
    for (int k = 0; k < FIN; k++) {
        float w = Ws[k * HID + c];
#pragma unroll
        for (int j = 0; j < 8; j++)
            acc[j] += xs[rbase + 4 * j][k] * w;
    }
#pragma unroll
    for (int j = 0; j < 8; j++) {
        int r = row0 + rbase + 4 * j;
        if (r < n) g_h1[r * HID + c] = acc[j] * g_dinv[r];
    }
}

// ---- aggregate layer 1: warp per node, unrolled x4 for MLP ----
__global__ void k_agg1(const float* __restrict__ b1, int n) {
    int node = blockIdx.x * 8 + (threadIdx.x >> 5);
    if (node >= n) return;
    int lane = threadIdx.x & 31;
    int e = g_off[node];
    int end = g_off[node + 1];
    float a0 = 0.0f, a1 = 0.0f;
    for (; e + 4 <= end; e += 4) {
        int s0 = g_esrc[e];
        int s1 = g_esrc[e + 1];
        int s2 = g_esrc[e + 2];
        int s3 = g_esrc[e + 3];
        const float* r0 = g_h1 + s0 * HID;
        const float* r1 = g_h1 + s1 * HID;
        const float* r2 = g_h1 + s2 * HID;
        const float* r3 = g_h1 + s3 * HID;
        float u0 = r0[lane],      u1 = r1[lane],      u2 = r2[lane],      u3 = r3[lane];
        float v0 = r0[lane + 32], v1 = r1[lane + 32], v2 = r2[lane + 32], v3 = r3[lane + 32];
        a0 += (u0 + u1) + (u2 + u3);
        a1 += (v0 + v1) + (v2 + v3);
    }
    for (; e < end; e++) {
        const float* row = g_h1 + g_esrc[e] * HID;
        a0 += row[lane];
        a1 += row[lane + 32];
    }
    float di = g_dinv[node];
    const float* self = g_h1 + node * HID;
    float o0 = (a0 + self[lane]) * di + b1[lane];
    float o1 = (a1 + self[lane + 32]) * di + b1[lane + 32];
    g_act1[node * HID + lane]      = o0 > 0.0f ? o0 : 0.0f;
    g_act1[node * HID + lane + 32] = o1 > 0.0f ? o1 : 0.0f;
}

// ---- GEMM2: h2[r,:] = (act1[r,:] @ W2) * dinv[r] ----
__global__ void k_gemm2(const float* __restrict__ W, int n) {
    __shared__ float Ws[HID * NCLS];
    __shared__ float xs[64][HID + 1];
    int t = threadIdx.x;
    for (int i = t; i < HID * NCLS; i += 256) Ws[i] = W[i];
    int row0 = blockIdx.x * 64;
    for (int i = t; i < 64 * HID; i += 256) {
        int r = i >> 6, k = i & 63;
        int gr = row0 + r;
        xs[r][k] = (gr < n) ? g_act1[gr * HID + k] : 0.0f;
    }
    __syncthreads();

    int c = t & 15;
    int rt = t >> 4;
    float acc[4];
#pragma unroll
    for (int j = 0; j < 4; j++) acc[j] = 0.0f;
#pragma unroll
    for (int k = 0; k < HID; k++) {
        float w = Ws[k * NCLS + c];
#pragma unroll
        for (int j = 0; j < 4; j++)
            acc[j] += xs[rt + 16 * j][k] * w;
    }
#pragma unroll
    for (int j = 0; j < 4; j++) {
        int r = row0 + rt + 16 * j;
        if (r < n) g_h2[r * NCLS + c] = acc[j] * g_dinv[r];
    }
}

// ---- aggregate layer 2: half-warp per node, unrolled x4 ----
__global__ void k_agg2(const float* __restrict__ b2, float* __restrict__ out, int n) {
    int node = blockIdx.x * 16 + (threadIdx.x >> 4);
    if (node >= n) return;
    int lane = threadIdx.x & 15;
    int e = g_off[node];
    int end = g_off[node + 1];
    float a = 0.0f;
    for (; e + 4 <= end; e += 4) {
        int s0 = g_esrc[e];
        int s1 = g_esrc[e + 1];
        int s2 = g_esrc[e + 2];
        int s3 = g_esrc[e + 3];
        float u0 = g_h2[s0 * NCLS + lane];
        float u1 = g_h2[s1 * NCLS + lane];
        float u2 = g_h2[s2 * NCLS + lane];
        float u3 = g_h2[s3 * NCLS + lane];
        a += (u0 + u1) + (u2 + u3);
    }
    for (; e < end; e++) {
        a += g_h2[g_esrc[e] * NCLS + lane];
    }
    float di = g_dinv[node];
    out[node * NCLS + lane] = (a + g_h2[node * NCLS + lane]) * di + b2[lane];
}

extern "C" void kernel_launch(void* const* d_in, const int* in_sizes, int n_in,
                              void* d_out, int out_size) {
    const float* x = (const float*)d_in[0];
    const void* ei = d_in[1];
    const float* W1 = (const float*)d_in[2];
    const float* b1 = (const float*)d_in[3];
    const float* W2 = (const float*)d_in[4];
    const float* b2 = (const float*)d_in[5];
    float* out = (float*)d_out;

    int n = in_sizes[0] / FIN;   // 50000
    int E = in_sizes[1] / 2;     // 800000

    k_zero_detect<<<(n + 255) / 256, 256>>>((const long long*)ei, n);
    k_detect<<<1, 64>>>((const long long*)ei);
    k_hist<<<(E + 255) / 256, 256>>>(ei, E);
    k_dinv<<<(n + 255) / 256, 256>>>(n);
    k_scan<<<1, 1024>>>(n);
    k_fill<<<(E + 255) / 256, 256>>>(ei, E);

    k_gemm1<<<(n + 31) / 32, 256>>>(x, W1, n);
    k_agg1<<<(n + 7) / 8, 256>>>(b1, n);

    k_gemm2<<<(n + 63) / 64, 256>>>(W2, n);
    k_agg2<<<(n + 15) / 16, 256>>>(b2, out, n);
}

// round 6
// speedup vs baseline: 1.5214x; 1.2778x over previous
#include <cuda_runtime.h>
#include <cuda_bf16.h>

// 2-layer GCN: x[50000,64], edge_index[2,800000], W1[64,64], b1[64],
// W2[64,16], b2[16] -> out[50000,16] f32.
//
// R4 @170.7us. R5 (resubmit; infra failure last round): float4 gathers with
// high MLP, 8 launches (was 10), dinv recomputed at use (rsqrt of CSR degree),
// g_off folded into g_pos, vectorized GEMM smem reads. CSR-by-dst + gather
// aggregation, no float atomics.

#define NN 50000
#define FIN 64
#define HID 64
#define NCLS 16
#define EMAX 800000

__device__ int   g_is32;           // 1 if edge_index is int32
__device__ int   g_cnt[NN];        // in-degree histogram (by dst)
__device__ int   g_pos[NN];        // scan: start offsets; after fill: end offsets
__device__ int   g_esrc[EMAX];     // src node per CSR slot
__device__ float g_h1[NN * HID];   // (x@W1) * dinv[row]
__device__ float g_act1[NN * HID]; // relu layer-1 output
__device__ float g_h2[NN * NCLS];  // (act1@W2) * dinv[row]

__device__ __forceinline__ int load_idx(const void* ei, int i, int is32) {
    int v;
    if (is32) v = ((const int*)ei)[i];
    else      v = (int)((const long long*)ei)[i];
    if (v < 0) v = 0;
    if (v >= NN) v = NN - 1;
    return v;
}

// ---- zero histogram + detect dtype (int64-read of int32 pairs leaves [0,NN)) ----
__global__ void k_zero_detect(const long long* __restrict__ ei, int n) {
    int i = blockIdx.x * blockDim.x + threadIdx.x;
    if (i < n) g_cnt[i] = 0;
    if (i == 0) {
        int bad = 0;
#pragma unroll
        for (int j = 0; j < 64; j++) {
            long long v = ei[j];
            if (v < 0 || v >= NN) bad = 1;
        }
        g_is32 = bad;
    }
}

// ---- histogram of dst ----
__global__ void k_hist(const void* __restrict__ ei, int E) {
    int e = blockIdx.x * blockDim.x + threadIdx.x;
    if (e >= E) return;
    atomicAdd(&g_cnt[load_idx(ei, E + e, g_is32)], 1);
}

// ---- single-block exclusive scan of g_cnt -> g_pos (start offsets) ----
__global__ void k_scan(int n) {
    __shared__ int partial[1024];
    int t = threadIdx.x;
    int chunk = (n + 1023) / 1024;
    int lo = t * chunk;
    int hi = lo + chunk; if (hi > n) hi = n;
    if (lo > n) lo = n;
    int s = 0;
    for (int i = lo; i < hi; i++) s += g_cnt[i];
    partial[t] = s;
    __syncthreads();
    for (int d = 1; d < 1024; d <<= 1) {
        int v = (t >= d) ? partial[t - d] : 0;
        __syncthreads();
        partial[t] += v;
        __syncthreads();
    }
    int base = (t == 0) ? 0 : partial[t - 1];
    for (int i = lo; i < hi; i++) {
        int c = g_cnt[i];
        g_pos[i] = base;
        base += c;
    }
}

// ---- fill CSR (after this, g_pos[d] = end offset of node d) ----
__global__ void k_fill(const void* __restrict__ ei, int E) {
    int e = blockIdx.x * blockDim.x + threadIdx.x;
    if (e >= E) return;
    int is32 = g_is32;
    int s = load_idx(ei, e, is32);
    int d = load_idx(ei, E + e, is32);
    int p = atomicAdd(&g_pos[d], 1);
    if (p >= 0 && p < EMAX) g_esrc[p] = s;
}

// ---- GEMM1: h1[r,:] = (x[r,:] @ W1) * rsqrt(deg[r]+1) ----
// 256 thr: c = t&63, rbase = t>>6 (warp-uniform); 8 rows per thread.
__global__ void k_gemm1(const float* __restrict__ x, const float* __restrict__ W,
                        int n) {
    __shared__ float Ws[FIN * HID];
    __shared__ __align__(16) float xs[32][FIN];
    int t = threadIdx.x;
    for (int i = t; i < (FIN * HID) / 4; i += 256)
        ((float4*)Ws)[i] = ((const float4*)W)[i];
    int row0 = blockIdx.x * 32;
    if (row0 + 32 <= n) {
        for (int i = t; i < (32 * FIN) / 4; i += 256)
            ((float4*)xs)[i] = ((const float4*)(x + row0 * FIN))[i];
    } else {
        for (int i = t; i < 32 * FIN; i += 256) {
            int r = i >> 6, k = i & 63;
            int gr = row0 + r;
            xs[r][k] = (gr < n) ? x[gr * FIN + k] : 0.0f;
        }
    }
    __syncthreads();

    int c = t & 63;
    int rbase = t >> 6;
    float acc[8];
#pragma unroll
    for (int j = 0; j < 8; j++) acc[j] = 0.0f;
#pragma unroll
    for (int k = 0; k < FIN; k += 4) {
        float w0 = Ws[(k + 0) * HID + c];
        float w1 = Ws[(k + 1) * HID + c];
        float w2 = Ws[(k + 2) * HID + c];
        float w3 = Ws[(k + 3) * HID + c];
#pragma unroll
        for (int j = 0; j < 8; j++) {
            float4 xv = *(const float4*)&xs[rbase + 4 * j][k];  // warp-broadcast
            acc[j] += xv.x * w0 + xv.y * w1 + xv.z * w2 + xv.w * w3;
        }
    }
#pragma unroll
    for (int j = 0; j < 8; j++) {
        int r = row0 + rbase + 4 * j;
        if (r < n) g_h1[r * HID + c] = acc[j] * rsqrtf((float)g_cnt[r] + 1.0f);
    }
}

// ---- agg layer 1: warp/node; half-warp per edge, float4 lanes, unroll x2 ----
__global__ void k_agg1(const float* __restrict__ b1, int n) {
    int node = blockIdx.x * 8 + (threadIdx.x >> 5);
    if (node >= n) return;
    int lane = threadIdx.x & 31;
    int h = lane >> 4;   // half-warp: which edge of a pair
    int q = lane & 15;   // float4 chunk within 64-float row
    int start = (node > 0) ? g_pos[node - 1] : 0;
    int end = g_pos[node];
    float4 a = make_float4(0.f, 0.f, 0.f, 0.f);
    int e = start + h;
    for (; e + 2 < end; e += 4) {   // edges e and e+2 for this half
        int s0 = g_esrc[e];
        int s1 = g_esrc[e + 2];
        float4 u0 = *(const float4*)(g_h1 + s0 * HID + q * 4);
        float4 u1 = *(const float4*)(g_h1 + s1 * HID + q * 4);
        a.x += u0.x + u1.x; a.y += u0.y + u1.y;
        a.z += u0.z + u1.z; a.w += u0.w + u1.w;
    }
    for (; e < end; e += 2) {
        int s = g_esrc[e];
        float4 u = *(const float4*)(g_h1 + s * HID + q * 4);
        a.x += u.x; a.y += u.y; a.z += u.z; a.w += u.w;
    }
    a.x += __shfl_xor_sync(0xffffffffu, a.x, 16);
    a.y += __shfl_xor_sync(0xffffffffu, a.y, 16);
    a.z += __shfl_xor_sync(0xffffffffu, a.z, 16);
    a.w += __shfl_xor_sync(0xffffffffu, a.w, 16);
    if (h == 0) {
        float di = rsqrtf((float)(end - start) + 1.0f);
        float4 self = *(const float4*)(g_h1 + node * HID + q * 4);
        float4 bb = ((const float4*)b1)[q];
        float4 o;
        o.x = fmaxf((a.x + self.x) * di + bb.x, 0.0f);
        o.y = fmaxf((a.y + self.y) * di + bb.y, 0.0f);
        o.z = fmaxf((a.z + self.z) * di + bb.z, 0.0f);
        o.w = fmaxf((a.w + self.w) * di + bb.w, 0.0f);
        *(float4*)(g_act1 + node * HID + q * 4) = o;
    }
}

// ---- GEMM2: h2[r,:] = (act1[r,:] @ W2) * dinv[r] ----
__global__ void k_gemm2(const float* __restrict__ W, int n) {
    __shared__ float Ws[HID * NCLS];
    __shared__ __align__(16) float xs[64][HID + 4];
    int t = threadIdx.x;
    for (int i = t; i < HID * NCLS; i += 256) Ws[i] = W[i];
    int row0 = blockIdx.x * 64;
    for (int i = t; i < (64 * HID) / 4; i += 256) {
        int r = i >> 4, k4 = i & 15;   // 16 float4 per row
        int gr = row0 + r;
        float4 v = make_float4(0.f, 0.f, 0.f, 0.f);
        if (gr < n) v = *(const float4*)(g_act1 + gr * HID + k4 * 4);
        *(float4*)&xs[r][k4 * 4] = v;
    }
    __syncthreads();

    int c = t & 15;
    int rt = t >> 4;
    float acc[4];
#pragma unroll
    for (int j = 0; j < 4; j++) acc[j] = 0.0f;
#pragma unroll
    for (int k = 0; k < HID; k += 4) {
        float w0 = Ws[(k + 0) * NCLS + c];
        float w1 = Ws[(k + 1) * NCLS + c];
        float w2 = Ws[(k + 2) * NCLS + c];
        float w3 = Ws[(k + 3) * NCLS + c];
#pragma unroll
        for (int j = 0; j < 4; j++) {
            float4 xv = *(const float4*)&xs[rt + 16 * j][k];
            acc[j] += xv.x * w0 + xv.y * w1 + xv.z * w2 + xv.w * w3;
        }
    }
#pragma unroll
    for (int j = 0; j < 4; j++) {
        int r = row0 + rt + 16 * j;
        if (r < n) g_h2[r * NCLS + c] = acc[j] * rsqrtf((float)g_cnt[r] + 1.0f);
    }
}

// ---- agg layer 2: warp/node; 8 edges/iter (g=lane>>2), float4 (q=lane&3) ----
__global__ void k_agg2(const float* __restrict__ b2, float* __restrict__ out, int n) {
    int node = blockIdx.x * 8 + (threadIdx.x >> 5);
    if (node >= n) return;
    int lane = threadIdx.x & 31;
    int g = lane >> 2;   // edge slot within group of 8
    int q = lane & 3;    // float4 chunk within 16-float row
    int start = (node > 0) ? g_pos[node - 1] : 0;
    int end = g_pos[node];
    float4 a = make_float4(0.f, 0.f, 0.f, 0.f);
    int e = start + g;
    for (; e + 8 < end; e += 16) {   // edges e and e+8
        int s0 = g_esrc[e];
        int s1 = g_esrc[e + 8];
        float4 u0 = *(const float4*)(g_h2 + s0 * NCLS + q * 4);
        float4 u1 = *(const float4*)(g_h2 + s1 * NCLS + q * 4);
        a.x += u0.x + u1.x; a.y += u0.y + u1.y;
        a.z += u0.z + u1.z; a.w += u0.w + u1.w;
    }
    for (; e < end; e += 8) {
        int s = g_esrc[e];
        float4 u = *(const float4*)(g_h2 + s * NCLS + q * 4);
        a.x += u.x; a.y += u.y; a.z += u.z; a.w += u.w;
    }
#pragma unroll
    for (int m = 4; m <= 16; m <<= 1) {
        a.x += __shfl_xor_sync(0xffffffffu, a.x, m);
        a.y += __shfl_xor_sync(0xffffffffu, a.y, m);
        a.z += __shfl_xor_sync(0xffffffffu, a.z, m);
        a.w += __shfl_xor_sync(0xffffffffu, a.w, m);
    }
    if (lane < 4) {
        float di = rsqrtf((float)(end - start) + 1.0f);
        float4 self = *(const float4*)(g_h2 + node * NCLS + q * 4);
        float4 bb = ((const float4*)b2)[q];
        float4 o;
        o.x = (a.x + self.x) * di + bb.x;
        o.y = (a.y + self.y) * di + bb.y;
        o.z = (a.z + self.z) * di + bb.z;
        o.w = (a.w + self.w) * di + bb.w;
        *(float4*)(out + node * NCLS + q * 4) = o;
    }
}

extern "C" void kernel_launch(void* const* d_in, const int* in_sizes, int n_in,
                              void* d_out, int out_size) {
    const float* x = (const float*)d_in[0];
    const void* ei = d_in[1];
    const float* W1 = (const float*)d_in[2];
    const float* b1 = (const float*)d_in[3];
    const float* W2 = (const float*)d_in[4];
    const float* b2 = (const float*)d_in[5];
    float* out = (float*)d_out;

    int n = in_sizes[0] / FIN;   // 50000
    int E = in_sizes[1] / 2;     // 800000

    k_zero_detect<<<(n + 255) / 256, 256>>>((const long long*)ei, n);
    k_hist<<<(E + 255) / 256, 256>>>(ei, E);
    k_scan<<<1, 1024>>>(n);
    k_fill<<<(E + 255) / 256, 256>>>(ei, E);

    k_gemm1<<<(n + 31) / 32, 256>>>(x, W1, n);
    k_agg1<<<(n + 7) / 8, 256>>>(b1, n);

    k_gemm2<<<(n + 63) / 64, 256>>>(W2, n);
    k_agg2<<<(n + 7) / 8, 256>>>(b2, out, n);
}